// round 5
// baseline (speedup 1.0000x reference)
#include <cuda_runtime.h>
#include <cuda_bf16.h>

#define NMAX 100000
#define EMAX 1600000

typedef unsigned long long u64;

// Scratch (zero-init at load; offset_kernel re-zeroes g_deg, count resets g_total)
__device__ float4 g_selfA[NMAX * 8];
__device__ float4 g_projA[NMAX * 8];
__device__ float4 g_selfB[NMAX * 8];
__device__ float4 g_projB[NMAX * 8];
__device__ float  g_inv[NMAX];
__device__ unsigned int g_deg[NMAX];
__device__ int    g_start[NMAX];
__device__ int    g_fill[NMAX];     // after fill: row end
__device__ int    g_csr[EMAX];
__device__ int    g_total;

// ---- packed fp32x2 helpers (Blackwell FFMA2 pipe, PTX-only) ----
__device__ __forceinline__ u64 pack2(float x, float y) {
    u64 r; asm("mov.b64 %0, {%1,%2};" : "=l"(r) : "f"(x), "f"(y)); return r;
}
__device__ __forceinline__ void unpack2(u64 v, float& x, float& y) {
    asm("mov.b64 {%0,%1}, %2;" : "=f"(x), "=f"(y) : "l"(v));
}
__device__ __forceinline__ void fma2(u64& d, u64 a, u64 b) {
    asm("fma.rn.f32x2 %0, %1, %2, %0;" : "+l"(d) : "l"(a), "l"(b));
}

// ---------------------------------------------------------------------------
// Per-block dtype detect: int32 data reinterpreted as int64 overflows [0,n)
// w.h.p. within the first 32 entries. Returns via shared flag.
// ---------------------------------------------------------------------------
__device__ __forceinline__ int block_detect_is32(const void* ei, int n, int* s_flag) {
    if (threadIdx.x < 32) {
        long long v = ((const long long*)ei)[threadIdx.x];
        int bad = (v < 0 || v >= (long long)n) ? 1 : 0;
        unsigned b = __ballot_sync(0xffffffffu, bad);
        if (threadIdx.x == 0) *s_flag = b ? 1 : 0;
    }
    __syncthreads();
    return *s_flag;
}

__device__ __forceinline__ int load_idx(const void* ei, int is32, long long elem) {
    if (is32) return ((const int*)ei)[elem];
    return (int)((const long long*)ei)[elem];
}

// ---------------------------------------------------------------------------
// count: degree histogram (RED). Block 0 also resets g_total for this replay.
// ---------------------------------------------------------------------------
__global__ void count_kernel(const void* __restrict__ ei, int e, int n) {
    __shared__ int s_is32;
    int is32 = block_detect_is32(ei, n, &s_is32);
    if (blockIdx.x == 0 && threadIdx.x == 0) g_total = 0;
    int i = blockIdx.x * blockDim.x + threadIdx.x;
    if (i >= e) return;
    int d = load_idx(ei, is32, (long long)e + i);
    atomicAdd(&g_deg[d], 1u);
}

// ---------------------------------------------------------------------------
// offset: CSR row ranges via warp prefix + one global atomic per warp.
// Also computes 1/max(deg,1) and resets g_deg (replay invariant).
// ---------------------------------------------------------------------------
__global__ void offset_kernel(int n) {
    int i = blockIdx.x * 256 + threadIdx.x;
    int lane = threadIdx.x & 31;
    int deg = (i < n) ? (int)g_deg[i] : 0;
    int pre = deg;
#pragma unroll
    for (int o = 1; o < 32; o <<= 1) {
        int t = __shfl_up_sync(0xffffffffu, pre, o);
        if (lane >= o) pre += t;
    }
    int wsum = __shfl_sync(0xffffffffu, pre, 31);
    int base = 0;
    if (lane == 31) base = atomicAdd(&g_total, wsum);
    base = __shfl_sync(0xffffffffu, base, 31);
    if (i < n) {
        int start = base + pre - deg;
        g_start[i] = start;
        g_fill[i]  = start;
        g_inv[i]   = 1.0f / (float)(deg > 1 ? deg : 1);
        g_deg[i]   = 0u;
    }
}

// ---------------------------------------------------------------------------
// fill_proj: heterogeneous kernel. Blocks [0, fill_blocks) scatter edges
// into CSR (LTS-atomic-bound); remaining blocks run proj1
// (selfA = x@W_self1+b_self1 ; projA = x@W_neigh1, 4 nodes/warp, FFMA2)
// on otherwise-idle FMA/LDS pipes.
// ---------------------------------------------------------------------------
__global__ void fill_proj_kernel(const void* __restrict__ ei, int e, int n,
                                 const float* __restrict__ x,
                                 const float* __restrict__ Ws,
                                 const float* __restrict__ bs,
                                 const float* __restrict__ Wn,
                                 int fill_blocks) {
    __shared__ float2 sW2[64 * 32];
    __shared__ float  sbs[32];
    __shared__ int    s_is32;

    if (blockIdx.x < fill_blocks) {
        int is32 = block_detect_is32(ei, n, &s_is32);
        int i = blockIdx.x * blockDim.x + threadIdx.x;
        if (i >= e) return;
        int s = load_idx(ei, is32, i);
        int d = load_idx(ei, is32, (long long)e + i);
        int pos = atomicAdd(&g_fill[d], 1);
        g_csr[pos] = s;
        return;
    }

    // ---- proj path ----
    for (int i = threadIdx.x; i < 64 * 32; i += 256)
        sW2[i] = make_float2(Ws[i], Wn[i]);
    if (threadIdx.x < 32) sbs[threadIdx.x] = bs[threadIdx.x];
    __syncthreads();

    int bid = blockIdx.x - fill_blocks;
    int warp = threadIdx.x >> 5, lane = threadIdx.x & 31;
    int node0 = (bid * 8 + warp) * 4;
    if (node0 >= n) return;

    float xv0[4], xv1[4];
    u64 acc2[4];
#pragma unroll
    for (int i = 0; i < 4; i++) {
        int node = node0 + i;
        if (node < n) {
            xv0[i] = x[(size_t)node * 64 + lane];
            xv1[i] = x[(size_t)node * 64 + 32 + lane];
        } else { xv0[i] = 0.f; xv1[i] = 0.f; }
        acc2[i] = pack2(sbs[lane], 0.f);
    }
#pragma unroll
    for (int k = 0; k < 32; k++) {
        float2 w = sW2[k * 32 + lane];
        u64 wp = pack2(w.x, w.y);
#pragma unroll
        for (int i = 0; i < 4; i++) {
            float xk = __shfl_sync(0xffffffffu, xv0[i], k);
            fma2(acc2[i], wp, pack2(xk, xk));
        }
    }
#pragma unroll
    for (int k = 0; k < 32; k++) {
        float2 w = sW2[(32 + k) * 32 + lane];
        u64 wp = pack2(w.x, w.y);
#pragma unroll
        for (int i = 0; i < 4; i++) {
            float xk = __shfl_sync(0xffffffffu, xv1[i], k);
            fma2(acc2[i], wp, pack2(xk, xk));
        }
    }
#pragma unroll
    for (int i = 0; i < 4; i++) {
        int node = node0 + i;
        if (node < n) {
            float accs, accn; unpack2(acc2[i], accs, accn);
            ((float*)g_selfA)[(size_t)node * 32 + lane] = accs;
            ((float*)g_projA)[(size_t)node * 32 + lane] = accn;
        }
    }
}

// ---------------------------------------------------------------------------
// gather: batch 4 shfl+LDG.128 groups (16 neighbors) before accumulating
// -> MLP 4 against ~240cyc L2 latency. Two accumulator chains.
// Returns float4 of features (lane&7)*4..+3, replicated across lane>>3.
// ---------------------------------------------------------------------------
__device__ __forceinline__ float4 gather_sum4(const float4* __restrict__ proj4,
                                              int node, int lane) {
    int start = g_start[node], end = g_fill[node];
    int sub = lane >> 3, fl = lane & 7;
    float4 a0 = make_float4(0.f, 0.f, 0.f, 0.f);
    float4 a1 = make_float4(0.f, 0.f, 0.f, 0.f);
    for (int base = start; base < end; base += 32) {
        int rem = end - base;
        int m = rem < 32 ? rem : 32;
        int myid = (lane < m) ? g_csr[base + lane] : 0;
        int k = 0;
        for (; k + 16 <= m; k += 16) {
            int s0 = __shfl_sync(0xffffffffu, myid, k + sub);
            int s1 = __shfl_sync(0xffffffffu, myid, k + 4 + sub);
            int s2 = __shfl_sync(0xffffffffu, myid, k + 8 + sub);
            int s3 = __shfl_sync(0xffffffffu, myid, k + 12 + sub);
            float4 v0 = proj4[(size_t)s0 * 8 + fl];
            float4 v1 = proj4[(size_t)s1 * 8 + fl];
            float4 v2 = proj4[(size_t)s2 * 8 + fl];
            float4 v3 = proj4[(size_t)s3 * 8 + fl];
            a0.x += v0.x; a0.y += v0.y; a0.z += v0.z; a0.w += v0.w;
            a1.x += v1.x; a1.y += v1.y; a1.z += v1.z; a1.w += v1.w;
            a0.x += v2.x; a0.y += v2.y; a0.z += v2.z; a0.w += v2.w;
            a1.x += v3.x; a1.y += v3.y; a1.z += v3.z; a1.w += v3.w;
        }
        for (; k < m; k += 4) {
            int g = k + sub;
            int sid = __shfl_sync(0xffffffffu, myid, g);
            if (g < m) {
                float4 v = proj4[(size_t)sid * 8 + fl];
                a0.x += v.x; a0.y += v.y; a0.z += v.z; a0.w += v.w;
            }
        }
    }
    a0.x += a1.x; a0.y += a1.y; a0.z += a1.z; a0.w += a1.w;
#pragma unroll
    for (int o = 8; o <= 16; o <<= 1) {
        a0.x += __shfl_xor_sync(0xffffffffu, a0.x, o);
        a0.y += __shfl_xor_sync(0xffffffffu, a0.y, o);
        a0.z += __shfl_xor_sync(0xffffffffu, a0.z, o);
        a0.w += __shfl_xor_sync(0xffffffffu, a0.w, o);
    }
    return a0;
}

// ---------------------------------------------------------------------------
// gather_h4: gather+combine h for 4 nodes of this warp, stage via SMEM,
// reload as h[node][lane] regs.
// ---------------------------------------------------------------------------
__device__ __forceinline__ void gather_h4(const float4* __restrict__ proj4,
                                          const float4* __restrict__ self4,
                                          const float4* __restrict__ bn4s,
                                          float4* __restrict__ stage,
                                          int node0, int n, int lane,
                                          float h_reg[4],
                                          float4* out_x32_4 /*nullable*/) {
    int sub = lane >> 3, fl = lane & 7;
#pragma unroll
    for (int i = 0; i < 4; i++) {
        int node = node0 + i;
        if (node >= n) continue;
        float inv = g_inv[node];
        float4 s4 = self4[(size_t)node * 8 + fl];
        float4 b4 = bn4s[fl];
        float4 acc = gather_sum4(proj4, node, lane);
        float4 h4;
        h4.x = fmaxf(fmaf(acc.x, inv, b4.x + s4.x), 0.f);
        h4.y = fmaxf(fmaf(acc.y, inv, b4.y + s4.y), 0.f);
        h4.z = fmaxf(fmaf(acc.z, inv, b4.z + s4.z), 0.f);
        h4.w = fmaxf(fmaf(acc.w, inv, b4.w + s4.w), 0.f);
        if (sub == 0) {
            stage[i * 8 + fl] = h4;
            if (out_x32_4) out_x32_4[(size_t)node * 8 + fl] = h4;
        }
    }
    __syncwarp();
#pragma unroll
    for (int i = 0; i < 4; i++)
        h_reg[i] = ((const float*)stage)[i * 32 + lane];
}

// ---------------------------------------------------------------------------
// agg1: h1 = relu(mean(neigh projA)+b_neigh1+selfA);
//       selfB = h1@W_self2+b_self2 ; projB = h1@W_neigh2   (4 nodes/warp)
// ---------------------------------------------------------------------------
__global__ void agg_combine1_kernel(const float* __restrict__ Ws2,
                                    const float* __restrict__ bs2,
                                    const float* __restrict__ Wn2,
                                    const float* __restrict__ bn1, int n) {
    __shared__ float2 sW2[32 * 32];
    __shared__ float  sbs[32];
    __shared__ float4 sbn4[8];
    __shared__ float4 sh4[8 * 4 * 8];
    for (int i = threadIdx.x; i < 1024; i += 256)
        sW2[i] = make_float2(Ws2[i], Wn2[i]);
    if (threadIdx.x < 32) sbs[threadIdx.x] = bs2[threadIdx.x];
    if (threadIdx.x < 8) sbn4[threadIdx.x] = ((const float4*)bn1)[threadIdx.x];
    __syncthreads();

    int warp = threadIdx.x >> 5, lane = threadIdx.x & 31;
    int node0 = (blockIdx.x * 8 + warp) * 4;
    if (node0 >= n) return;

    float h_reg[4];
    gather_h4(g_projA, g_selfA, sbn4, &sh4[warp * 32], node0, n, lane, h_reg, nullptr);

    u64 acc2[4];
#pragma unroll
    for (int i = 0; i < 4; i++) acc2[i] = pack2(sbs[lane], 0.f);
#pragma unroll
    for (int k = 0; k < 32; k++) {
        float2 w = sW2[k * 32 + lane];
        u64 wp = pack2(w.x, w.y);
#pragma unroll
        for (int i = 0; i < 4; i++) {
            float hk = __shfl_sync(0xffffffffu, h_reg[i], k);
            fma2(acc2[i], wp, pack2(hk, hk));
        }
    }
#pragma unroll
    for (int i = 0; i < 4; i++) {
        int node = node0 + i;
        if (node < n) {
            float accs, accn; unpack2(acc2[i], accs, accn);
            ((float*)g_selfB)[(size_t)node * 32 + lane] = accs;
            ((float*)g_projB)[(size_t)node * 32 + lane] = accn;
        }
    }
}

// ---------------------------------------------------------------------------
// agg2: h2 = relu(mean(neigh projB)+b_neigh2+selfB);
//       x32 = h2 ; logits = h2@W_out+b_out   (4 nodes/warp)
// ---------------------------------------------------------------------------
__global__ void agg_combine2_kernel(const float* __restrict__ Wout,
                                    const float* __restrict__ bout,
                                    const float* __restrict__ bn2, int n,
                                    float* __restrict__ out_x32,
                                    float* __restrict__ out_logits) {
    __shared__ float2 sW2[32 * 32];
    __shared__ float  sb[40];
    __shared__ float4 sbn4[8];
    __shared__ float4 sh4[8 * 4 * 8];
    for (int i = threadIdx.x; i < 1024; i += 256) {
        int k = i >> 5, l = i & 31;
        sW2[i] = make_float2(Wout[k * 40 + l], Wout[k * 40 + 32 + (l & 7)]);
    }
    if (threadIdx.x < 40) sb[threadIdx.x] = bout[threadIdx.x];
    if (threadIdx.x < 8) sbn4[threadIdx.x] = ((const float4*)bn2)[threadIdx.x];
    __syncthreads();

    int warp = threadIdx.x >> 5, lane = threadIdx.x & 31;
    int node0 = (blockIdx.x * 8 + warp) * 4;
    if (node0 >= n) return;

    float h_reg[4];
    gather_h4(g_projB, g_selfB, sbn4, &sh4[warp * 32], node0, n, lane, h_reg,
              (float4*)out_x32);

    u64 acc2[4];
#pragma unroll
    for (int i = 0; i < 4; i++)
        acc2[i] = pack2(sb[lane], (lane < 8) ? sb[32 + lane] : 0.f);
#pragma unroll
    for (int k = 0; k < 32; k++) {
        float2 w = sW2[k * 32 + lane];
        u64 wp = pack2(w.x, w.y);
#pragma unroll
        for (int i = 0; i < 4; i++) {
            float hk = __shfl_sync(0xffffffffu, h_reg[i], k);
            fma2(acc2[i], wp, pack2(hk, hk));
        }
    }
#pragma unroll
    for (int i = 0; i < 4; i++) {
        int node = node0 + i;
        if (node < n) {
            float a0, a1; unpack2(acc2[i], a0, a1);
            out_logits[(size_t)node * 40 + lane] = a0;
            if (lane < 8) out_logits[(size_t)node * 40 + 32 + lane] = a1;
        }
    }
}

// ---------------------------------------------------------------------------
// Launch. Output: concat(x32 [N,32], logits [N,40]) fp32. W_lin1 is dead code.
// ---------------------------------------------------------------------------
extern "C" void kernel_launch(void* const* d_in, const int* in_sizes, int n_in,
                              void* d_out, int out_size) {
    const float* x    = (const float*)d_in[0];
    const void*  ei   = d_in[1];
    const float* Ws1  = (const float*)d_in[2];
    const float* bs1  = (const float*)d_in[3];
    const float* Wn1  = (const float*)d_in[4];
    const float* bn1  = (const float*)d_in[5];
    const float* Ws2  = (const float*)d_in[6];
    const float* bs2  = (const float*)d_in[7];
    const float* Wn2  = (const float*)d_in[8];
    const float* bn2  = (const float*)d_in[9];
    const float* Wout = (const float*)d_in[10];
    const float* bout = (const float*)d_in[11];

    int n = in_sizes[0] / 64;
    int e = in_sizes[1] / 2;

    float* out        = (float*)d_out;
    float* out_x32    = out;
    float* out_logits = out + (size_t)n * 32;

    int node_blocks = (n + 31) / 32;   // 8 warps x 4 nodes
    int nb256       = (n + 255) / 256;
    int eb256       = (e + 255) / 256;

    count_kernel<<<eb256, 256>>>(ei, e, n);
    offset_kernel<<<nb256, 256>>>(n);
    fill_proj_kernel<<<eb256 + node_blocks, 256>>>(ei, e, n, x, Ws1, bs1, Wn1, eb256);
    agg_combine1_kernel<<<node_blocks, 256>>>(Ws2, bs2, Wn2, bn1, n);
    agg_combine2_kernel<<<node_blocks, 256>>>(Wout, bout, bn2, n, out_x32, out_logits);
}

// round 6
// speedup vs baseline: 1.0423x; 1.0423x over previous
#include <cuda_runtime.h>
#include <cuda_bf16.h>

#define NMAX 100000
#define EMAX 1600000

typedef unsigned long long u64;

// Scratch (zero-init at load; offset_kernel re-zeroes g_deg, count resets g_total)
__device__ float4 g_selfA[NMAX * 8];
__device__ float4 g_projA[NMAX * 8];
__device__ float4 g_selfB[NMAX * 8];
__device__ float4 g_projB[NMAX * 8];
__device__ float  g_inv[NMAX];
__device__ unsigned int g_deg[NMAX];
__device__ int    g_start[NMAX];
__device__ int    g_fill[NMAX];     // after fill: row end
__device__ int    g_csr[EMAX];
__device__ int    g_total;

// ---- packed fp32x2 helpers (Blackwell FFMA2 pipe, PTX-only) ----
__device__ __forceinline__ u64 pack2(float x, float y) {
    u64 r; asm("mov.b64 %0, {%1,%2};" : "=l"(r) : "f"(x), "f"(y)); return r;
}
__device__ __forceinline__ void unpack2(u64 v, float& x, float& y) {
    asm("mov.b64 {%0,%1}, %2;" : "=f"(x), "=f"(y) : "l"(v));
}
__device__ __forceinline__ void fma2(u64& d, u64 a, u64 b) {
    asm("fma.rn.f32x2 %0, %1, %2, %0;" : "+l"(d) : "l"(a), "l"(b));
}

// ---------------------------------------------------------------------------
// Per-block dtype detect: int32 data reinterpreted as int64 overflows [0,n)
// w.h.p. within the first 32 entries.
// ---------------------------------------------------------------------------
__device__ __forceinline__ int block_detect_is32(const void* ei, int n, int* s_flag) {
    if (threadIdx.x < 32) {
        long long v = ((const long long*)ei)[threadIdx.x];
        int bad = (v < 0 || v >= (long long)n) ? 1 : 0;
        unsigned b = __ballot_sync(0xffffffffu, bad);
        if (threadIdx.x == 0) *s_flag = b ? 1 : 0;
    }
    __syncthreads();
    return *s_flag;
}

__device__ __forceinline__ int load_idx(const void* ei, int is32, long long elem) {
    if (is32) return ((const int*)ei)[elem];
    return (int)((const long long*)ei)[elem];
}

// ---------------------------------------------------------------------------
// count: degree histogram (RED). Block 0 also resets g_total for this replay.
// ---------------------------------------------------------------------------
__global__ void count_kernel(const void* __restrict__ ei, int e, int n) {
    __shared__ int s_is32;
    int is32 = block_detect_is32(ei, n, &s_is32);
    if (blockIdx.x == 0 && threadIdx.x == 0) g_total = 0;
    int i = blockIdx.x * blockDim.x + threadIdx.x;
    if (i >= e) return;
    int d = load_idx(ei, is32, (long long)e + i);
    atomicAdd(&g_deg[d], 1u);
}

// ---------------------------------------------------------------------------
// offset: CSR row ranges via warp prefix + one global atomic per warp.
// Also computes 1/max(deg,1) and resets g_deg (replay invariant).
// ---------------------------------------------------------------------------
__global__ void offset_kernel(int n) {
    int i = blockIdx.x * 256 + threadIdx.x;
    int lane = threadIdx.x & 31;
    int deg = (i < n) ? (int)g_deg[i] : 0;
    int pre = deg;
#pragma unroll
    for (int o = 1; o < 32; o <<= 1) {
        int t = __shfl_up_sync(0xffffffffu, pre, o);
        if (lane >= o) pre += t;
    }
    int wsum = __shfl_sync(0xffffffffu, pre, 31);
    int base = 0;
    if (lane == 31) base = atomicAdd(&g_total, wsum);
    base = __shfl_sync(0xffffffffu, base, 31);
    if (i < n) {
        int start = base + pre - deg;
        g_start[i] = start;
        g_fill[i]  = start;
        g_inv[i]   = 1.0f / (float)(deg > 1 ? deg : 1);
        g_deg[i]   = 0u;
    }
}

// ---------------------------------------------------------------------------
// fill_proj: heterogeneous kernel. Blocks [0, fill_blocks) scatter edges
// into CSR; remaining blocks run proj1 (selfA = x@W_self1+b_self1 ;
// projA = x@W_neigh1, 4 nodes/warp, FFMA2) on otherwise-idle pipes.
// ---------------------------------------------------------------------------
__global__ void fill_proj_kernel(const void* __restrict__ ei, int e, int n,
                                 const float* __restrict__ x,
                                 const float* __restrict__ Ws,
                                 const float* __restrict__ bs,
                                 const float* __restrict__ Wn,
                                 int fill_blocks) {
    __shared__ float2 sW2[64 * 32];
    __shared__ float  sbs[32];
    __shared__ int    s_is32;

    if (blockIdx.x < fill_blocks) {
        int is32 = block_detect_is32(ei, n, &s_is32);
        int i = blockIdx.x * blockDim.x + threadIdx.x;
        if (i >= e) return;
        int s = load_idx(ei, is32, i);
        int d = load_idx(ei, is32, (long long)e + i);
        int pos = atomicAdd(&g_fill[d], 1);
        g_csr[pos] = s;
        return;
    }

    // ---- proj path ----
    for (int i = threadIdx.x; i < 64 * 32; i += 256)
        sW2[i] = make_float2(Ws[i], Wn[i]);
    if (threadIdx.x < 32) sbs[threadIdx.x] = bs[threadIdx.x];
    __syncthreads();

    int bid = blockIdx.x - fill_blocks;
    int warp = threadIdx.x >> 5, lane = threadIdx.x & 31;
    int node0 = (bid * 8 + warp) * 4;
    if (node0 >= n) return;

    float xv0[4], xv1[4];
    u64 acc2[4];
#pragma unroll
    for (int i = 0; i < 4; i++) {
        int node = node0 + i;
        if (node < n) {
            xv0[i] = x[(size_t)node * 64 + lane];
            xv1[i] = x[(size_t)node * 64 + 32 + lane];
        } else { xv0[i] = 0.f; xv1[i] = 0.f; }
        acc2[i] = pack2(sbs[lane], 0.f);
    }
#pragma unroll
    for (int k = 0; k < 32; k++) {
        float2 w = sW2[k * 32 + lane];
        u64 wp = pack2(w.x, w.y);
#pragma unroll
        for (int i = 0; i < 4; i++) {
            float xk = __shfl_sync(0xffffffffu, xv0[i], k);
            fma2(acc2[i], wp, pack2(xk, xk));
        }
    }
#pragma unroll
    for (int k = 0; k < 32; k++) {
        float2 w = sW2[(32 + k) * 32 + lane];
        u64 wp = pack2(w.x, w.y);
#pragma unroll
        for (int i = 0; i < 4; i++) {
            float xk = __shfl_sync(0xffffffffu, xv1[i], k);
            fma2(acc2[i], wp, pack2(xk, xk));
        }
    }
#pragma unroll
    for (int i = 0; i < 4; i++) {
        int node = node0 + i;
        if (node < n) {
            float accs, accn; unpack2(acc2[i], accs, accn);
            ((float*)g_selfA)[(size_t)node * 32 + lane] = accs;
            ((float*)g_projA)[(size_t)node * 32 + lane] = accn;
        }
    }
}

// ---------------------------------------------------------------------------
// gather_h4: all 4 nodes of the warp gathered in LOCKSTEP WAVES — 4
// independent LDG.128 per wave (one per node) -> cross-node MLP ~16 with
// unroll, no inter-node dependence. Then combine -> h (staged via SMEM).
// ---------------------------------------------------------------------------
__device__ __forceinline__ void gather_h4(const float4* __restrict__ proj4,
                                          const float4* __restrict__ self4,
                                          const float4* __restrict__ bn4s,
                                          float4* __restrict__ stage,
                                          int node0, int n, int lane,
                                          float h_reg[4],
                                          float4* out_x32_4 /*nullable*/) {
    int sub = lane >> 3, fl = lane & 7;
    const char* pbase = (const char*)proj4;
    unsigned flo = (unsigned)fl << 4;

    float4 acc[4];
    int off[4], rem[4];
#pragma unroll
    for (int i = 0; i < 4; i++) {
        int node = node0 + i;
        if (node < n) { int s = g_start[node]; off[i] = s; rem[i] = g_fill[node] - s; }
        else { off[i] = 0; rem[i] = 0; }
        acc[i] = make_float4(0.f, 0.f, 0.f, 0.f);
    }

    for (;;) {
        int m[4], id[4], mmax = 0;
#pragma unroll
        for (int i = 0; i < 4; i++) {
            m[i] = rem[i] < 32 ? rem[i] : 32;
            if (m[i] > mmax) mmax = m[i];
            id[i] = (lane < m[i]) ? g_csr[off[i] + lane] : 0;
        }
#pragma unroll 2
        for (int kk = 0; kk < mmax; kk += 4) {
            int g = kk + sub;                    // <= 31 always
#pragma unroll
            for (int i = 0; i < 4; i++) {
                int sid = __shfl_sync(0xffffffffu, id[i], g);
                if (g < m[i]) {
                    float4 v = *(const float4*)(pbase + (((unsigned)sid << 7) | flo));
                    acc[i].x += v.x; acc[i].y += v.y;
                    acc[i].z += v.z; acc[i].w += v.w;
                }
            }
        }
        int any = 0;
#pragma unroll
        for (int i = 0; i < 4; i++) { off[i] += m[i]; rem[i] -= m[i]; any |= rem[i]; }
        if (!any) break;
    }

    // reduce across the 4 sub-groups
#pragma unroll
    for (int i = 0; i < 4; i++) {
#pragma unroll
        for (int o = 8; o <= 16; o <<= 1) {
            acc[i].x += __shfl_xor_sync(0xffffffffu, acc[i].x, o);
            acc[i].y += __shfl_xor_sync(0xffffffffu, acc[i].y, o);
            acc[i].z += __shfl_xor_sync(0xffffffffu, acc[i].z, o);
            acc[i].w += __shfl_xor_sync(0xffffffffu, acc[i].w, o);
        }
    }

    // combine: h = relu(mean + bias + self)
#pragma unroll
    for (int i = 0; i < 4; i++) {
        int node = node0 + i;
        if (node >= n) continue;
        float inv = g_inv[node];
        float4 s4 = self4[(size_t)node * 8 + fl];
        float4 b4 = bn4s[fl];
        float4 h4;
        h4.x = fmaxf(fmaf(acc[i].x, inv, b4.x + s4.x), 0.f);
        h4.y = fmaxf(fmaf(acc[i].y, inv, b4.y + s4.y), 0.f);
        h4.z = fmaxf(fmaf(acc[i].z, inv, b4.z + s4.z), 0.f);
        h4.w = fmaxf(fmaf(acc[i].w, inv, b4.w + s4.w), 0.f);
        if (sub == 0) {
            stage[i * 8 + fl] = h4;
            if (out_x32_4) out_x32_4[(size_t)node * 8 + fl] = h4;
        }
    }
    __syncwarp();
#pragma unroll
    for (int i = 0; i < 4; i++)
        h_reg[i] = ((const float*)stage)[i * 32 + lane];
}

// ---------------------------------------------------------------------------
// agg1: h1 = relu(mean(neigh projA)+b_neigh1+selfA);
//       selfB = h1@W_self2+b_self2 ; projB = h1@W_neigh2   (4 nodes/warp)
// ---------------------------------------------------------------------------
__global__ void agg_combine1_kernel(const float* __restrict__ Ws2,
                                    const float* __restrict__ bs2,
                                    const float* __restrict__ Wn2,
                                    const float* __restrict__ bn1, int n) {
    __shared__ float2 sW2[32 * 32];
    __shared__ float  sbs[32];
    __shared__ float4 sbn4[8];
    __shared__ float4 sh4[8 * 4 * 8];
    for (int i = threadIdx.x; i < 1024; i += 256)
        sW2[i] = make_float2(Ws2[i], Wn2[i]);
    if (threadIdx.x < 32) sbs[threadIdx.x] = bs2[threadIdx.x];
    if (threadIdx.x < 8) sbn4[threadIdx.x] = ((const float4*)bn1)[threadIdx.x];
    __syncthreads();

    int warp = threadIdx.x >> 5, lane = threadIdx.x & 31;
    int node0 = (blockIdx.x * 8 + warp) * 4;
    if (node0 >= n) return;

    float h_reg[4];
    gather_h4(g_projA, g_selfA, sbn4, &sh4[warp * 32], node0, n, lane, h_reg, nullptr);

    u64 acc2[4];
#pragma unroll
    for (int i = 0; i < 4; i++) acc2[i] = pack2(sbs[lane], 0.f);
#pragma unroll
    for (int k = 0; k < 32; k++) {
        float2 w = sW2[k * 32 + lane];
        u64 wp = pack2(w.x, w.y);
#pragma unroll
        for (int i = 0; i < 4; i++) {
            float hk = __shfl_sync(0xffffffffu, h_reg[i], k);
            fma2(acc2[i], wp, pack2(hk, hk));
        }
    }
#pragma unroll
    for (int i = 0; i < 4; i++) {
        int node = node0 + i;
        if (node < n) {
            float accs, accn; unpack2(acc2[i], accs, accn);
            ((float*)g_selfB)[(size_t)node * 32 + lane] = accs;
            ((float*)g_projB)[(size_t)node * 32 + lane] = accn;
        }
    }
}

// ---------------------------------------------------------------------------
// agg2: h2 = relu(mean(neigh projB)+b_neigh2+selfB);
//       x32 = h2 ; logits = h2@W_out+b_out   (4 nodes/warp)
// ---------------------------------------------------------------------------
__global__ void agg_combine2_kernel(const float* __restrict__ Wout,
                                    const float* __restrict__ bout,
                                    const float* __restrict__ bn2, int n,
                                    float* __restrict__ out_x32,
                                    float* __restrict__ out_logits) {
    __shared__ float2 sW2[32 * 32];
    __shared__ float  sb[40];
    __shared__ float4 sbn4[8];
    __shared__ float4 sh4[8 * 4 * 8];
    for (int i = threadIdx.x; i < 1024; i += 256) {
        int k = i >> 5, l = i & 31;
        sW2[i] = make_float2(Wout[k * 40 + l], Wout[k * 40 + 32 + (l & 7)]);
    }
    if (threadIdx.x < 40) sb[threadIdx.x] = bout[threadIdx.x];
    if (threadIdx.x < 8) sbn4[threadIdx.x] = ((const float4*)bn2)[threadIdx.x];
    __syncthreads();

    int warp = threadIdx.x >> 5, lane = threadIdx.x & 31;
    int node0 = (blockIdx.x * 8 + warp) * 4;
    if (node0 >= n) return;

    float h_reg[4];
    gather_h4(g_projB, g_selfB, sbn4, &sh4[warp * 32], node0, n, lane, h_reg,
              (float4*)out_x32);

    u64 acc2[4];
#pragma unroll
    for (int i = 0; i < 4; i++)
        acc2[i] = pack2(sb[lane], (lane < 8) ? sb[32 + lane] : 0.f);
#pragma unroll
    for (int k = 0; k < 32; k++) {
        float2 w = sW2[k * 32 + lane];
        u64 wp = pack2(w.x, w.y);
#pragma unroll
        for (int i = 0; i < 4; i++) {
            float hk = __shfl_sync(0xffffffffu, h_reg[i], k);
            fma2(acc2[i], wp, pack2(hk, hk));
        }
    }
#pragma unroll
    for (int i = 0; i < 4; i++) {
        int node = node0 + i;
        if (node < n) {
            float a0, a1; unpack2(acc2[i], a0, a1);
            out_logits[(size_t)node * 40 + lane] = a0;
            if (lane < 8) out_logits[(size_t)node * 40 + 32 + lane] = a1;
        }
    }
}

// ---------------------------------------------------------------------------
// Launch. Output: concat(x32 [N,32], logits [N,40]) fp32. W_lin1 is dead code.
// ---------------------------------------------------------------------------
extern "C" void kernel_launch(void* const* d_in, const int* in_sizes, int n_in,
                              void* d_out, int out_size) {
    const float* x    = (const float*)d_in[0];
    const void*  ei   = d_in[1];
    const float* Ws1  = (const float*)d_in[2];
    const float* bs1  = (const float*)d_in[3];
    const float* Wn1  = (const float*)d_in[4];
    const float* bn1  = (const float*)d_in[5];
    const float* Ws2  = (const float*)d_in[6];
    const float* bs2  = (const float*)d_in[7];
    const float* Wn2  = (const float*)d_in[8];
    const float* bn2  = (const float*)d_in[9];
    const float* Wout = (const float*)d_in[10];
    const float* bout = (const float*)d_in[11];

    int n = in_sizes[0] / 64;
    int e = in_sizes[1] / 2;

    float* out        = (float*)d_out;
    float* out_x32    = out;
    float* out_logits = out + (size_t)n * 32;

    int node_blocks = (n + 31) / 32;   // 8 warps x 4 nodes
    int nb256       = (n + 255) / 256;
    int eb256       = (e + 255) / 256;

    count_kernel<<<eb256, 256>>>(ei, e, n);
    offset_kernel<<<nb256, 256>>>(n);
    fill_proj_kernel<<<eb256 + node_blocks, 256>>>(ei, e, n, x, Ws1, bs1, Wn1, eb256);
    agg_combine1_kernel<<<node_blocks, 256>>>(Ws2, bs2, Wn2, bn1, n);
    agg_combine2_kernel<<<node_blocks, 256>>>(Wout, bout, bn2, n, out_x32, out_logits);
}

// round 7
// speedup vs baseline: 1.1873x; 1.1391x over previous
#include <cuda_runtime.h>
#include <cuda_bf16.h>

#define NMAX 100000
#define EMAX 1600000
#define CSRMAX (EMAX + 3 * NMAX + 8)   // rows padded to multiple of 4

typedef unsigned long long u64;

// Scratch (zero-init at load; offset_kernel restores g_deg, count resets g_total).
// proj arrays have a sentinel zero row at index NMAX (never written).
__device__ float4 g_selfA[NMAX * 8];
__device__ float4 g_projA[(NMAX + 1) * 8];
__device__ float4 g_selfB[NMAX * 8];
__device__ float4 g_projB[(NMAX + 1) * 8];
__device__ float  g_inv[NMAX];
__device__ unsigned int g_deg[NMAX];
__device__ int    g_start[NMAX];
__device__ int    g_end4[NMAX];     // padded row end (start + ceil4(deg))
__device__ int    g_fill[NMAX];     // fill cursor
__device__ int    g_csr[CSRMAX];
__device__ int    g_total;

// ---- packed fp32x2 helpers (Blackwell FFMA2/FADD2 pipe, PTX-only) ----
__device__ __forceinline__ u64 pack2(float x, float y) {
    u64 r; asm("mov.b64 %0, {%1,%2};" : "=l"(r) : "f"(x), "f"(y)); return r;
}
__device__ __forceinline__ void unpack2(u64 v, float& x, float& y) {
    asm("mov.b64 {%0,%1}, %2;" : "=f"(x), "=f"(y) : "l"(v));
}
__device__ __forceinline__ void fma2(u64& d, u64 a, u64 b) {
    asm("fma.rn.f32x2 %0, %1, %2, %0;" : "+l"(d) : "l"(a), "l"(b));
}
__device__ __forceinline__ void add2(u64& d, u64 a) {
    asm("add.rn.f32x2 %0, %0, %1;" : "+l"(d) : "l"(a));
}

// ---------------------------------------------------------------------------
// Per-block dtype detect: int32 data reinterpreted as int64 overflows [0,n)
// w.h.p. within the first 32 entries.
// ---------------------------------------------------------------------------
__device__ __forceinline__ int block_detect_is32(const void* ei, int n, int* s_flag) {
    if (threadIdx.x < 32) {
        long long v = ((const long long*)ei)[threadIdx.x];
        int bad = (v < 0 || v >= (long long)n) ? 1 : 0;
        unsigned b = __ballot_sync(0xffffffffu, bad);
        if (threadIdx.x == 0) *s_flag = b ? 1 : 0;
    }
    __syncthreads();
    return *s_flag;
}

__device__ __forceinline__ int load_idx(const void* ei, int is32, long long elem) {
    if (is32) return ((const int*)ei)[elem];
    return (int)((const long long*)ei)[elem];
}

// ---------------------------------------------------------------------------
// count: degree histogram (RED). Block 0 also resets g_total for this replay.
// ---------------------------------------------------------------------------
__global__ void count_kernel(const void* __restrict__ ei, int e, int n) {
    __shared__ int s_is32;
    int is32 = block_detect_is32(ei, n, &s_is32);
    if (blockIdx.x == 0 && threadIdx.x == 0) g_total = 0;
    int i = blockIdx.x * blockDim.x + threadIdx.x;
    if (i >= e) return;
    int d = load_idx(ei, is32, (long long)e + i);
    atomicAdd(&g_deg[d], 1u);
}

// ---------------------------------------------------------------------------
// offset: 4-aligned CSR row ranges (warp prefix over padded degree + one
// global atomic per warp). Writes sentinel ids (NMAX) into the padding so the
// gather loop needs no tail handling. Resets g_deg (replay invariant).
// ---------------------------------------------------------------------------
__global__ void offset_kernel(int n) {
    int i = blockIdx.x * 256 + threadIdx.x;
    int lane = threadIdx.x & 31;
    int deg = (i < n) ? (int)g_deg[i] : 0;
    int pdeg = (deg + 3) & ~3;
    int pre = pdeg;
#pragma unroll
    for (int o = 1; o < 32; o <<= 1) {
        int t = __shfl_up_sync(0xffffffffu, pre, o);
        if (lane >= o) pre += t;
    }
    int wsum = __shfl_sync(0xffffffffu, pre, 31);
    int base = 0;
    if (lane == 31) base = atomicAdd(&g_total, wsum);
    base = __shfl_sync(0xffffffffu, base, 31);
    if (i < n) {
        int start = base + pre - pdeg;
        g_start[i] = start;
        g_fill[i]  = start;
        g_end4[i]  = start + pdeg;
#pragma unroll
        for (int p = 0; p < 3; p++)
            if (deg + p < pdeg) g_csr[start + deg + p] = NMAX;   // sentinel
        g_inv[i] = 1.0f / (float)(deg > 1 ? deg : 1);
        g_deg[i] = 0u;
    }
}

// ---------------------------------------------------------------------------
// fill_proj: heterogeneous kernel. Blocks [0, fill_blocks) scatter edges
// into CSR; remaining blocks run proj1 (selfA = x@W_self1+b_self1 ;
// projA = x@W_neigh1, 4 nodes/warp, FFMA2) on otherwise-idle pipes.
// ---------------------------------------------------------------------------
__global__ void fill_proj_kernel(const void* __restrict__ ei, int e, int n,
                                 const float* __restrict__ x,
                                 const float* __restrict__ Ws,
                                 const float* __restrict__ bs,
                                 const float* __restrict__ Wn,
                                 int fill_blocks) {
    __shared__ float2 sW2[64 * 32];
    __shared__ float  sbs[32];
    __shared__ int    s_is32;

    if (blockIdx.x < fill_blocks) {
        int is32 = block_detect_is32(ei, n, &s_is32);
        int i = blockIdx.x * blockDim.x + threadIdx.x;
        if (i >= e) return;
        int s = load_idx(ei, is32, i);
        int d = load_idx(ei, is32, (long long)e + i);
        int pos = atomicAdd(&g_fill[d], 1);
        g_csr[pos] = s;
        return;
    }

    // ---- proj path ----
    for (int i = threadIdx.x; i < 64 * 32; i += 256)
        sW2[i] = make_float2(Ws[i], Wn[i]);
    if (threadIdx.x < 32) sbs[threadIdx.x] = bs[threadIdx.x];
    __syncthreads();

    int bid = blockIdx.x - fill_blocks;
    int warp = threadIdx.x >> 5, lane = threadIdx.x & 31;
    int node0 = (bid * 8 + warp) * 4;
    if (node0 >= n) return;

    float xv0[4], xv1[4];
    u64 acc2[4];
#pragma unroll
    for (int i = 0; i < 4; i++) {
        int node = node0 + i;
        if (node < n) {
            xv0[i] = x[(size_t)node * 64 + lane];
            xv1[i] = x[(size_t)node * 64 + 32 + lane];
        } else { xv0[i] = 0.f; xv1[i] = 0.f; }
        acc2[i] = pack2(sbs[lane], 0.f);
    }
#pragma unroll
    for (int k = 0; k < 32; k++) {
        float2 w = sW2[k * 32 + lane];
        u64 wp = pack2(w.x, w.y);
#pragma unroll
        for (int i = 0; i < 4; i++) {
            float xk = __shfl_sync(0xffffffffu, xv0[i], k);
            fma2(acc2[i], wp, pack2(xk, xk));
        }
    }
#pragma unroll
    for (int k = 0; k < 32; k++) {
        float2 w = sW2[(32 + k) * 32 + lane];
        u64 wp = pack2(w.x, w.y);
#pragma unroll
        for (int i = 0; i < 4; i++) {
            float xk = __shfl_sync(0xffffffffu, xv1[i], k);
            fma2(acc2[i], wp, pack2(xk, xk));
        }
    }
#pragma unroll
    for (int i = 0; i < 4; i++) {
        int node = node0 + i;
        if (node < n) {
            float accs, accn; unpack2(acc2[i], accs, accn);
            ((float*)g_selfA)[(size_t)node * 32 + lane] = accs;
            ((float*)g_projA)[(size_t)node * 32 + lane] = accn;
        }
    }
}

// ---------------------------------------------------------------------------
// gather_h4: each 8-lane group owns ONE node. Shfl-free: ids come as one
// int4 broadcast load per 4 edges (padded CSR, sentinel -> zero row), rows
// as 4 independent LDG.128, accumulation in f32x2 with 2 chains.
// h staged via SMEM -> h_reg[i] = h[node i][lane].
// ---------------------------------------------------------------------------
__device__ __forceinline__ void gather_h4(const float4* __restrict__ proj4,
                                          const float4* __restrict__ self4,
                                          const float4* __restrict__ bn4s,
                                          float4* __restrict__ stage,
                                          int node0, int n, int lane,
                                          float h_reg[4],
                                          float4* out_x32_4 /*nullable*/) {
    int grp = lane >> 3, fl = lane & 7;
    int node = node0 + grp;
    bool valid = node < n;
    int p  = valid ? g_start[node] : 0;
    int pe = valid ? g_end4[node] : 0;

    const char* pb = (const char*)proj4;
    unsigned flo = (unsigned)fl << 4;
    u64 aA0 = pack2(0.f, 0.f), aA1 = aA0, aB0 = aA0, aB1 = aA0;

#pragma unroll 2
    for (; p < pe; p += 4) {
        int4 ids = *(const int4*)&g_csr[p];       // 16B broadcast within group
        float4 v0 = *(const float4*)(pb + (((unsigned)ids.x << 7) | flo));
        float4 v1 = *(const float4*)(pb + (((unsigned)ids.y << 7) | flo));
        float4 v2 = *(const float4*)(pb + (((unsigned)ids.z << 7) | flo));
        float4 v3 = *(const float4*)(pb + (((unsigned)ids.w << 7) | flo));
        add2(aA0, pack2(v0.x, v0.y)); add2(aB0, pack2(v0.z, v0.w));
        add2(aA1, pack2(v1.x, v1.y)); add2(aB1, pack2(v1.z, v1.w));
        add2(aA0, pack2(v2.x, v2.y)); add2(aB0, pack2(v2.z, v2.w));
        add2(aA1, pack2(v3.x, v3.y)); add2(aB1, pack2(v3.z, v3.w));
    }
    add2(aA0, aA1); add2(aB0, aB1);
    float ax, ay, az, aw;
    unpack2(aA0, ax, ay); unpack2(aB0, az, aw);

    if (valid) {
        float inv = g_inv[node];
        float4 s4 = self4[(size_t)node * 8 + fl];
        float4 b4 = bn4s[fl];
        float4 h4;
        h4.x = fmaxf(fmaf(ax, inv, b4.x + s4.x), 0.f);
        h4.y = fmaxf(fmaf(ay, inv, b4.y + s4.y), 0.f);
        h4.z = fmaxf(fmaf(az, inv, b4.z + s4.z), 0.f);
        h4.w = fmaxf(fmaf(aw, inv, b4.w + s4.w), 0.f);
        stage[grp * 8 + fl] = h4;
        if (out_x32_4) out_x32_4[(size_t)node * 8 + fl] = h4;
    }
    __syncwarp();
#pragma unroll
    for (int i = 0; i < 4; i++)
        h_reg[i] = ((const float*)stage)[i * 32 + lane];
}

// ---------------------------------------------------------------------------
// agg1: h1 = relu(mean(neigh projA)+b_neigh1+selfA);
//       selfB = h1@W_self2+b_self2 ; projB = h1@W_neigh2   (4 nodes/warp)
// ---------------------------------------------------------------------------
__global__ void agg_combine1_kernel(const float* __restrict__ Ws2,
                                    const float* __restrict__ bs2,
                                    const float* __restrict__ Wn2,
                                    const float* __restrict__ bn1, int n) {
    __shared__ float2 sW2[32 * 32];
    __shared__ float  sbs[32];
    __shared__ float4 sbn4[8];
    __shared__ float4 sh4[8 * 4 * 8];
    for (int i = threadIdx.x; i < 1024; i += 256)
        sW2[i] = make_float2(Ws2[i], Wn2[i]);
    if (threadIdx.x < 32) sbs[threadIdx.x] = bs2[threadIdx.x];
    if (threadIdx.x < 8) sbn4[threadIdx.x] = ((const float4*)bn1)[threadIdx.x];
    __syncthreads();

    int warp = threadIdx.x >> 5, lane = threadIdx.x & 31;
    int node0 = (blockIdx.x * 8 + warp) * 4;
    if (node0 >= n) return;

    float h_reg[4];
    gather_h4(g_projA, g_selfA, sbn4, &sh4[warp * 32], node0, n, lane, h_reg, nullptr);

    u64 acc2[4];
#pragma unroll
    for (int i = 0; i < 4; i++) acc2[i] = pack2(sbs[lane], 0.f);
#pragma unroll
    for (int k = 0; k < 32; k++) {
        float2 w = sW2[k * 32 + lane];
        u64 wp = pack2(w.x, w.y);
#pragma unroll
        for (int i = 0; i < 4; i++) {
            float hk = __shfl_sync(0xffffffffu, h_reg[i], k);
            fma2(acc2[i], wp, pack2(hk, hk));
        }
    }
#pragma unroll
    for (int i = 0; i < 4; i++) {
        int node = node0 + i;
        if (node < n) {
            float accs, accn; unpack2(acc2[i], accs, accn);
            ((float*)g_selfB)[(size_t)node * 32 + lane] = accs;
            ((float*)g_projB)[(size_t)node * 32 + lane] = accn;
        }
    }
}

// ---------------------------------------------------------------------------
// agg2: h2 = relu(mean(neigh projB)+b_neigh2+selfB);
//       x32 = h2 ; logits = h2@W_out+b_out   (4 nodes/warp)
// ---------------------------------------------------------------------------
__global__ void agg_combine2_kernel(const float* __restrict__ Wout,
                                    const float* __restrict__ bout,
                                    const float* __restrict__ bn2, int n,
                                    float* __restrict__ out_x32,
                                    float* __restrict__ out_logits) {
    __shared__ float2 sW2[32 * 32];
    __shared__ float  sb[40];
    __shared__ float4 sbn4[8];
    __shared__ float4 sh4[8 * 4 * 8];
    for (int i = threadIdx.x; i < 1024; i += 256) {
        int k = i >> 5, l = i & 31;
        sW2[i] = make_float2(Wout[k * 40 + l], Wout[k * 40 + 32 + (l & 7)]);
    }
    if (threadIdx.x < 40) sb[threadIdx.x] = bout[threadIdx.x];
    if (threadIdx.x < 8) sbn4[threadIdx.x] = ((const float4*)bn2)[threadIdx.x];
    __syncthreads();

    int warp = threadIdx.x >> 5, lane = threadIdx.x & 31;
    int node0 = (blockIdx.x * 8 + warp) * 4;
    if (node0 >= n) return;

    float h_reg[4];
    gather_h4(g_projB, g_selfB, sbn4, &sh4[warp * 32], node0, n, lane, h_reg,
              (float4*)out_x32);

    u64 acc2[4];
#pragma unroll
    for (int i = 0; i < 4; i++)
        acc2[i] = pack2(sb[lane], (lane < 8) ? sb[32 + lane] : 0.f);
#pragma unroll
    for (int k = 0; k < 32; k++) {
        float2 w = sW2[k * 32 + lane];
        u64 wp = pack2(w.x, w.y);
#pragma unroll
        for (int i = 0; i < 4; i++) {
            float hk = __shfl_sync(0xffffffffu, h_reg[i], k);
            fma2(acc2[i], wp, pack2(hk, hk));
        }
    }
#pragma unroll
    for (int i = 0; i < 4; i++) {
        int node = node0 + i;
        if (node < n) {
            float a0, a1; unpack2(acc2[i], a0, a1);
            out_logits[(size_t)node * 40 + lane] = a0;
            if (lane < 8) out_logits[(size_t)node * 40 + 32 + lane] = a1;
        }
    }
}

// ---------------------------------------------------------------------------
// Launch. Output: concat(x32 [N,32], logits [N,40]) fp32. W_lin1 is dead code.
// ---------------------------------------------------------------------------
extern "C" void kernel_launch(void* const* d_in, const int* in_sizes, int n_in,
                              void* d_out, int out_size) {
    const float* x    = (const float*)d_in[0];
    const void*  ei   = d_in[1];
    const float* Ws1  = (const float*)d_in[2];
    const float* bs1  = (const float*)d_in[3];
    const float* Wn1  = (const float*)d_in[4];
    const float* bn1  = (const float*)d_in[5];
    const float* Ws2  = (const float*)d_in[6];
    const float* bs2  = (const float*)d_in[7];
    const float* Wn2  = (const float*)d_in[8];
    const float* bn2  = (const float*)d_in[9];
    const float* Wout = (const float*)d_in[10];
    const float* bout = (const float*)d_in[11];

    int n = in_sizes[0] / 64;
    int e = in_sizes[1] / 2;

    float* out        = (float*)d_out;
    float* out_x32    = out;
    float* out_logits = out + (size_t)n * 32;

    int node_blocks = (n + 31) / 32;   // 8 warps x 4 nodes
    int nb256       = (n + 255) / 256;
    int eb256       = (e + 255) / 256;

    count_kernel<<<eb256, 256>>>(ei, e, n);
    offset_kernel<<<nb256, 256>>>(n);
    fill_proj_kernel<<<eb256 + node_blocks, 256>>>(ei, e, n, x, Ws1, bs1, Wn1, eb256);
    agg_combine1_kernel<<<node_blocks, 256>>>(Ws2, bs2, Wn2, bn1, n);
    agg_combine2_kernel<<<node_blocks, 256>>>(Wout, bout, bn2, n, out_x32, out_logits);
}